// round 1
// baseline (speedup 1.0000x reference)
#include <cuda_runtime.h>
#include <math.h>
#include <stddef.h>

#define B    16
#define CIN  512
#define COUT 512
#define HH   64
#define WW   64
#define SD   512
#define EPS  1e-8f

// 1/sqrt(512), 1/sqrt(512*9)
#define MOD_SCALE  0.04419417382415922f
#define CONV_SCALE 0.014731391274719738f

#define BOC 64   // out-channels per block
#define CK  8    // input-channel chunk

__device__ float g_s[B * CIN];       // modulation s[b][i]
__device__ float g_demod[B * COUT];  // demod[b][oc]

// ---------------------------------------------------------------------------
// Kernel 1: s[b][i] = MOD_SCALE * (style[b,:] . mod_weight[i,:]) + mod_bias[i]
// grid = CIN blocks, 256 threads; block computes s[:, i] for all 16 b.
// ---------------------------------------------------------------------------
__global__ __launch_bounds__(256) void mod_kernel(
    const float* __restrict__ style,
    const float* __restrict__ mw,
    const float* __restrict__ mb)
{
    const int i = blockIdx.x;
    const int t = threadIdx.x;

    __shared__ float sh_style[B * SD];   // 32 KB
    __shared__ float sh_w[SD];
    __shared__ float red[8][B];

    for (int idx = t; idx < B * SD; idx += 256) sh_style[idx] = style[idx];
    for (int d = t; d < SD; d += 256)           sh_w[d] = mw[(size_t)i * SD + d];
    __syncthreads();

    float acc[B];
#pragma unroll
    for (int b = 0; b < B; b++) acc[b] = 0.f;

    for (int d = t; d < SD; d += 256) {
        const float wv = sh_w[d];
#pragma unroll
        for (int b = 0; b < B; b++) acc[b] += wv * sh_style[b * SD + d];
    }

#pragma unroll
    for (int off = 16; off > 0; off >>= 1) {
#pragma unroll
        for (int b = 0; b < B; b++)
            acc[b] += __shfl_down_sync(0xffffffffu, acc[b], off);
    }
    const int warp = t >> 5, lane = t & 31;
    if (lane == 0) {
#pragma unroll
        for (int b = 0; b < B; b++) red[warp][b] = acc[b];
    }
    __syncthreads();
    if (t < B) {
        float v = 0.f;
#pragma unroll
        for (int w = 0; w < 8; w++) v += red[w][t];
        g_s[t * CIN + i] = v * MOD_SCALE + mb[i];
    }
}

// ---------------------------------------------------------------------------
// Kernel 2: demod[b][oc] = rsqrt(CONV_SCALE^2 * sum_i wsq[oc,i]*s[b,i]^2 + eps)
// grid = COUT blocks, 256 threads.
// ---------------------------------------------------------------------------
__global__ __launch_bounds__(256) void demod_kernel(const float* __restrict__ cw)
{
    const int oc = blockIdx.x;
    const int t  = threadIdx.x;

    __shared__ float red[8][B];

    float acc[B];
#pragma unroll
    for (int b = 0; b < B; b++) acc[b] = 0.f;

    for (int i = t; i < CIN; i += 256) {
        const float* wp = cw + ((size_t)oc * CIN + i) * 9;
        float wsq = 0.f;
#pragma unroll
        for (int k = 0; k < 9; k++) { const float v = wp[k]; wsq += v * v; }
#pragma unroll
        for (int b = 0; b < B; b++) {
            const float s = g_s[b * CIN + i];
            acc[b] += wsq * s * s;
        }
    }

#pragma unroll
    for (int off = 16; off > 0; off >>= 1) {
#pragma unroll
        for (int b = 0; b < B; b++)
            acc[b] += __shfl_down_sync(0xffffffffu, acc[b], off);
    }
    const int warp = t >> 5, lane = t & 31;
    if (lane == 0) {
#pragma unroll
        for (int b = 0; b < B; b++) red[warp][b] = acc[b];
    }
    __syncthreads();
    if (t < B) {
        float v = 0.f;
#pragma unroll
        for (int w = 0; w < 8; w++) v += red[w][t];
        g_demod[t * COUT + oc] = rsqrtf(CONV_SCALE * CONV_SCALE * v + EPS);
    }
}

// ---------------------------------------------------------------------------
// Kernel 3: main conv.
//  out[b,oc,h,w] = demod[b,oc] * sum_{ci,kh,kw} W[oc,ci,kh,kw] *
//                  (CONV_SCALE * s[b,ci] * x[b,ci,h+kh-1,w+kw-1])
//  block: 64 oc x (8x8 spatial) for one b; thread: 4 oc x 4 w.
// ---------------------------------------------------------------------------
__global__ __launch_bounds__(256) void conv_kernel(
    const float* __restrict__ x,
    const float* __restrict__ cw,
    float* __restrict__ out)
{
    const int b   = blockIdx.z;
    const int oc0 = blockIdx.y * BOC;
    const int th0 = (blockIdx.x >> 3) * 8;   // tile row origin
    const int tw0 = (blockIdx.x & 7) * 8;    // tile col origin

    const int tid   = threadIdx.x;
    const int toc   = tid >> 4;      // 0..15 -> oc group of 4
    const int tsp   = tid & 15;      // 0..15 -> spatial group
    const int r     = tsp >> 1;      // 0..7  local output row
    const int wbase = (tsp & 1) * 4; // 0 or 4: local output col base

    // sW[oc][ci*9+k], pad row to 73 floats (conflict-free fill + read)
    __shared__ float sW[BOC][CK * 9 + 1];       // 64*73*4 = 18,688 B
    // sX[ci][row 0..9][col 0..12], stride 13 -> 16 distinct banks per warp read
    __shared__ float sX[CK][10][13];            // 4,160 B

    float acc[4][4];
#pragma unroll
    for (int i = 0; i < 4; i++)
#pragma unroll
        for (int j = 0; j < 4; j++) acc[i][j] = 0.f;

    for (int ci0 = 0; ci0 < CIN; ci0 += CK) {
        // ---- fill weights (gmem-coalesced 288B runs per oc) ----
        for (int idx = tid; idx < BOC * 72; idx += 256) {
            const int oc = idx / 72;
            const int j  = idx - oc * 72;    // ci*9 + k, ci in [0,CK)
            sW[oc][j] = cw[(size_t)(oc0 + oc) * (CIN * 9) + (size_t)ci0 * 9 + j];
        }
        // ---- fill scaled input tile with halo ----
        for (int idx = tid; idx < CK * 100; idx += 256) {
            const int ci  = idx / 100;
            const int rem = idx - ci * 100;
            const int rr  = rem / 10;
            const int cc  = rem - rr * 10;
            const int hg  = th0 - 1 + rr;
            const int wg  = tw0 - 1 + cc;
            float v = 0.f;
            if ((unsigned)hg < (unsigned)HH && (unsigned)wg < (unsigned)WW) {
                const float sv = CONV_SCALE * g_s[b * CIN + ci0 + ci];
                v = sv * x[(((size_t)b * CIN + ci0 + ci) * HH + hg) * WW + wg];
            }
            sX[ci][rr][cc] = v;
        }
        __syncthreads();

        // ---- compute ----
#pragma unroll
        for (int ci = 0; ci < CK; ci++) {
#pragma unroll
            for (int kh = 0; kh < 3; kh++) {
                float xv[6];
#pragma unroll
                for (int j = 0; j < 6; j++)
                    xv[j] = sX[ci][r + kh][wbase + j];
#pragma unroll
                for (int kw = 0; kw < 3; kw++) {
                    const int k = ci * 9 + kh * 3 + kw;
                    const float w0 = sW[toc * 4 + 0][k];
                    const float w1 = sW[toc * 4 + 1][k];
                    const float w2 = sW[toc * 4 + 2][k];
                    const float w3 = sW[toc * 4 + 3][k];
#pragma unroll
                    for (int u = 0; u < 4; u++) {
                        const float xx = xv[kw + u];
                        acc[0][u] += w0 * xx;
                        acc[1][u] += w1 * xx;
                        acc[2][u] += w2 * xx;
                        acc[3][u] += w3 * xx;
                    }
                }
            }
        }
        __syncthreads();
    }

    // ---- epilogue: apply demod, vectorized store ----
    const int h  = th0 + r;
    const int wg = tw0 + wbase;
#pragma unroll
    for (int i = 0; i < 4; i++) {
        const int oc  = oc0 + toc * 4 + i;
        const float d = g_demod[b * COUT + oc];
        float4 v;
        v.x = acc[i][0] * d;
        v.y = acc[i][1] * d;
        v.z = acc[i][2] * d;
        v.w = acc[i][3] * d;
        *reinterpret_cast<float4*>(
            &out[(((size_t)b * COUT + oc) * HH + h) * WW + wg]) = v;
    }
}

// ---------------------------------------------------------------------------
extern "C" void kernel_launch(void* const* d_in, const int* in_sizes, int n_in,
                              void* d_out, int out_size)
{
    const float* input       = (const float*)d_in[0];
    const float* style       = (const float*)d_in[1];
    const float* conv_weight = (const float*)d_in[2];  // [1,512,512,3,3]
    const float* mod_weight  = (const float*)d_in[3];  // [512,512]
    const float* mod_bias    = (const float*)d_in[4];  // [512]
    float* out = (float*)d_out;

    mod_kernel<<<CIN, 256>>>(style, mod_weight, mod_bias);
    demod_kernel<<<COUT, 256>>>(conv_weight);

    dim3 grid(64, COUT / BOC, B);   // 64 spatial tiles x 8 oc-blocks x 16 batch
    conv_kernel<<<grid, 256>>>(input, conv_weight, out);
}

// round 3
// speedup vs baseline: 3.5418x; 3.5418x over previous
#include <cuda_runtime.h>
#include <cuda_fp16.h>
#include <mma.h>
#include <math.h>
#include <stddef.h>
#include <stdint.h>

using namespace nvcuda;

#define B    16
#define CIN  512
#define COUT 512
#define HH   64
#define WW   64
#define SD   512
#define EPS  1e-8f

#define MOD_SCALE  0.04419417382415922f   // 1/sqrt(512)
#define CONV_SCALE 0.014731391274719738f  // 1/sqrt(512*9)

// padded, channel-last, scaled input: [B][66][66][512] fp16 hi/lo
#define XP 66
static __device__ __half g_xs_hi[(size_t)B * XP * XP * CIN];
static __device__ __half g_xs_lo[(size_t)B * XP * XP * CIN];
// weights channel-last per tap: [9][512 oc][512 ci] fp16 hi/lo
static __device__ __half g_wt_hi[9 * COUT * CIN];
static __device__ __half g_wt_lo[9 * COUT * CIN];
__device__ float g_s[B * CIN];
__device__ float g_demod[B * COUT];

__device__ __forceinline__ uint32_t smem_u32(const void* p) {
    uint32_t a;
    asm("{ .reg .u64 t; cvta.to.shared.u64 t, %1; cvt.u32.u64 %0, t; }"
        : "=r"(a) : "l"(p));
    return a;
}

// ---------------------------------------------------------------------------
// Kernel 1: s[b][i] = MOD_SCALE * (style[b,:] . mod_weight[i,:]) + mod_bias[i]
// ---------------------------------------------------------------------------
__global__ __launch_bounds__(256) void mod_kernel(
    const float* __restrict__ style, const float* __restrict__ mw,
    const float* __restrict__ mb)
{
    const int i = blockIdx.x, t = threadIdx.x;
    __shared__ float sh_style[B * SD];
    __shared__ float sh_w[SD];
    __shared__ float red[8][B];
    for (int idx = t; idx < B * SD; idx += 256) sh_style[idx] = style[idx];
    for (int d = t; d < SD; d += 256)           sh_w[d] = mw[(size_t)i * SD + d];
    __syncthreads();
    float acc[B];
#pragma unroll
    for (int b = 0; b < B; b++) acc[b] = 0.f;
    for (int d = t; d < SD; d += 256) {
        const float wv = sh_w[d];
#pragma unroll
        for (int b = 0; b < B; b++) acc[b] += wv * sh_style[b * SD + d];
    }
#pragma unroll
    for (int off = 16; off > 0; off >>= 1)
#pragma unroll
        for (int b = 0; b < B; b++)
            acc[b] += __shfl_down_sync(0xffffffffu, acc[b], off);
    const int warp = t >> 5, lane = t & 31;
    if (lane == 0)
#pragma unroll
        for (int b = 0; b < B; b++) red[warp][b] = acc[b];
    __syncthreads();
    if (t < B) {
        float v = 0.f;
#pragma unroll
        for (int w = 0; w < 8; w++) v += red[w][t];
        g_s[t * CIN + i] = v * MOD_SCALE + mb[i];
    }
}

// ---------------------------------------------------------------------------
// Kernel 2: demod[b][oc] = rsqrt(CONV_SCALE^2 * sum_i wsq[oc,i]*s[b,i]^2 + eps)
// ---------------------------------------------------------------------------
__global__ __launch_bounds__(256) void demod_kernel(const float* __restrict__ cw)
{
    const int oc = blockIdx.x, t = threadIdx.x;
    __shared__ float red[8][B];
    float acc[B];
#pragma unroll
    for (int b = 0; b < B; b++) acc[b] = 0.f;
    for (int i = t; i < CIN; i += 256) {
        const float* wp = cw + ((size_t)oc * CIN + i) * 9;
        float wsq = 0.f;
#pragma unroll
        for (int k = 0; k < 9; k++) { const float v = wp[k]; wsq += v * v; }
#pragma unroll
        for (int b = 0; b < B; b++) {
            const float s = g_s[b * CIN + i];
            acc[b] += wsq * s * s;
        }
    }
#pragma unroll
    for (int off = 16; off > 0; off >>= 1)
#pragma unroll
        for (int b = 0; b < B; b++)
            acc[b] += __shfl_down_sync(0xffffffffu, acc[b], off);
    const int warp = t >> 5, lane = t & 31;
    if (lane == 0)
#pragma unroll
        for (int b = 0; b < B; b++) red[warp][b] = acc[b];
    __syncthreads();
    if (t < B) {
        float v = 0.f;
#pragma unroll
        for (int w = 0; w < 8; w++) v += red[w][t];
        g_demod[t * COUT + oc] = rsqrtf(CONV_SCALE * CONV_SCALE * v + EPS);
    }
}

// ---------------------------------------------------------------------------
// Kernel 3: weight split:  g_wt[tap][oc][ci] = fp16split(W[oc][ci][tap])
// ---------------------------------------------------------------------------
__global__ __launch_bounds__(256) void wsplit_kernel(const float* __restrict__ cw)
{
    int idx = blockIdx.x * 256 + threadIdx.x;      // 9*512*512
    int ci  = idx & 511;
    int t1  = idx >> 9;
    int oc  = t1 & 511;
    int tap = t1 >> 9;
    float v = cw[((size_t)(oc << 9) + ci) * 9 + tap];
    __half hi = __float2half(v);
    __half lo = __float2half(v - __half2float(hi));
    size_t dst = ((size_t)tap << 18) + ((size_t)oc << 9) + ci;
    g_wt_hi[dst] = hi;
    g_wt_lo[dst] = lo;
}

// ---------------------------------------------------------------------------
// Kernel 4: zero padded borders of g_xs_{hi,lo}
// ---------------------------------------------------------------------------
__global__ void border_kernel()
{
    int i = blockIdx.x;           // 16*260
    int b = i / 260, r = i % 260;
    int h, w;
    if      (r <  66) { h = 0;           w = r;        }
    else if (r < 132) { h = 65;          w = r - 66;   }
    else if (r < 196) { h = r - 132 + 1; w = 0;        }
    else              { h = r - 196 + 1; w = 65;       }
    size_t base = (((size_t)b * XP + h) * XP + w) * CIN;
    int t = threadIdx.x;          // 128 threads x 8B = 1KB = 512 halves
    *(uint2*)((char*)g_xs_hi + base * 2 + t * 8) = make_uint2(0, 0);
    *(uint2*)((char*)g_xs_lo + base * 2 + t * 8) = make_uint2(0, 0);
}

// ---------------------------------------------------------------------------
// Kernel 5: transpose + scale + split:  xs[b][h+1][w+1][ci] = fp16split(CONV_SCALE*s*x)
// ---------------------------------------------------------------------------
__global__ __launch_bounds__(256) void xtrans_kernel(const float* __restrict__ x)
{
    const int cic = blockIdx.x, h = blockIdx.y, b = blockIdx.z;
    const int tid = threadIdx.x;
    const int ci0 = cic * 64;
    __shared__ float sT[64 * 65];
    __shared__ float sS[64];
    if (tid < 64) sS[tid] = CONV_SCALE * g_s[b * CIN + ci0 + tid];
#pragma unroll
    for (int it = 0; it < 16; it++) {
        int idx = it * 256 + tid;
        int cl = idx >> 6, w = idx & 63;
        sT[cl * 65 + w] = x[(((size_t)(b * CIN + ci0 + cl)) * HH + h) * WW + w];
    }
    __syncthreads();
#pragma unroll
    for (int it = 0; it < 16; it++) {
        int idx = it * 256 + tid;
        int w = idx >> 6, cl = idx & 63;
        float v = sS[cl] * sT[cl * 65 + w];
        __half hi = __float2half(v);
        __half lo = __float2half(v - __half2float(hi));
        size_t dst = (((size_t)b * XP + h + 1) * XP + (w + 1)) * CIN + ci0 + cl;
        g_xs_hi[dst] = hi;
        g_xs_lo[dst] = lo;
    }
}

// ---------------------------------------------------------------------------
// Kernel 6: main wmma (HMMA) implicit-GEMM conv.
// CTA: 128 oc x 128 px (2h x 64w), 8 warps (warp tile 64x32).
// K: 144 iters = 9 taps x 16 ci-chunks(32); 2-stage cp.async double buffer.
// 3-pass fp16 split, fp32 accum, demod in epilogue.
// ---------------------------------------------------------------------------
#define LDM 40                      // 32 halves data + 8 pad (80B rows)
#define ARR_BYTES (128 * LDM * 2)   // 10240
#define STAGE_BYTES (4 * ARR_BYTES) // Ahi, Alo, Bhi, Blo = 40960
#define SMEM_DYN (2 * STAGE_BYTES)  // 81920

__device__ __forceinline__ void load_stage(uint32_t st_u32, int iter,
                                           int b, int h0, int oc0, int tid)
{
    const int tap = iter >> 4;
    const int cic = iter & 15;
    const int kh = tap / 3, kw = tap - 3 * kh;
    const int ci0 = cic * 32;
#pragma unroll
    for (int it = 0; it < 8; it++) {
        const int op  = it * 256 + tid;
        const int arr = op >> 9;          // compile-time per `it` parity pair
        const int r   = (op >> 2) & 127;
        const int c   = op & 3;
        uint32_t dst = st_u32 + arr * ARR_BYTES + r * 80 + c * 16;
        const __half* src;
        if (arr == 0)
            src = g_wt_hi + ((size_t)tap << 18) + ((size_t)(oc0 + r) << 9) + ci0 + c * 8;
        else if (arr == 1)
            src = g_wt_lo + ((size_t)tap << 18) + ((size_t)(oc0 + r) << 9) + ci0 + c * 8;
        else {
            const size_t po = ((((size_t)b * XP) + h0 + (r >> 6) + kh) * XP
                               + (r & 63) + kw) * CIN + ci0 + c * 8;
            src = (arr == 2 ? g_xs_hi : g_xs_lo) + po;
        }
        asm volatile("cp.async.ca.shared.global [%0], [%1], 16;"
                     :: "r"(dst), "l"(src));
    }
}

__global__ __launch_bounds__(256, 2) void conv_wmma_kernel(float* __restrict__ out)
{
    extern __shared__ char dynsmem[];
    const int tid = threadIdx.x;
    const int wid = tid >> 5;
    const int wm  = wid & 1;      // warp M block (64 oc)
    const int wn  = wid >> 1;     // warp N block (32 px)

    const int bx = blockIdx.x;    // 16 b x 32 h-groups
    const int b  = bx >> 5;
    const int h0 = (bx & 31) * 2;
    const int oc0 = blockIdx.y * 128;

    const uint32_t s_u32 = smem_u32(dynsmem);

    wmma::fragment<wmma::accumulator, 16, 16, 16, float> c[4][2];
#pragma unroll
    for (int mt = 0; mt < 4; mt++)
#pragma unroll
        for (int nt = 0; nt < 2; nt++) wmma::fill_fragment(c[mt][nt], 0.f);

    // prologue: stages 0,1
    load_stage(s_u32, 0, b, h0, oc0, tid);
    asm volatile("cp.async.commit_group;" ::: "memory");
    load_stage(s_u32 + STAGE_BYTES, 1, b, h0, oc0, tid);
    asm volatile("cp.async.commit_group;" ::: "memory");

    for (int iter = 0; iter < 144; iter++) {
        asm volatile("cp.async.wait_group 1;" ::: "memory");
        __syncthreads();

        const char* st = dynsmem + (iter & 1) * STAGE_BYTES;
        const __half* sAh = (const __half*)(st);
        const __half* sAl = (const __half*)(st + ARR_BYTES);
        const __half* sBh = (const __half*)(st + 2 * ARR_BYTES);
        const __half* sBl = (const __half*)(st + 3 * ARR_BYTES);

#pragma unroll
        for (int ks = 0; ks < 2; ks++) {
            wmma::fragment<wmma::matrix_b, 16, 16, 16, __half, wmma::col_major> bh[2], bl[2];
#pragma unroll
            for (int nt = 0; nt < 2; nt++) {
                const int prow = wn * 32 + nt * 16;
                wmma::load_matrix_sync(bh[nt], sBh + prow * LDM + ks * 16, LDM);
                wmma::load_matrix_sync(bl[nt], sBl + prow * LDM + ks * 16, LDM);
            }
#pragma unroll
            for (int mt = 0; mt < 4; mt++) {
                const int orow = wm * 64 + mt * 16;
                wmma::fragment<wmma::matrix_a, 16, 16, 16, __half, wmma::row_major> ah, al;
                wmma::load_matrix_sync(ah, sAh + orow * LDM + ks * 16, LDM);
                wmma::load_matrix_sync(al, sAl + orow * LDM + ks * 16, LDM);
#pragma unroll
                for (int nt = 0; nt < 2; nt++) {
                    wmma::mma_sync(c[mt][nt], ah, bh[nt], c[mt][nt]);
                    wmma::mma_sync(c[mt][nt], ah, bl[nt], c[mt][nt]);
                    wmma::mma_sync(c[mt][nt], al, bh[nt], c[mt][nt]);
                }
            }
        }
        __syncthreads();
        if (iter + 2 < 144) {
            load_stage(s_u32 + ((iter & 1) ? STAGE_BYTES : 0), iter + 2, b, h0, oc0, tid);
            asm volatile("cp.async.commit_group;" ::: "memory");
        }
    }

    // epilogue: accum -> SMEM [128 oc][132 px] -> demod-scaled coalesced STG
    float* ep = (float*)dynsmem;
#pragma unroll
    for (int mt = 0; mt < 4; mt++)
#pragma unroll
        for (int nt = 0; nt < 2; nt++)
            wmma::store_matrix_sync(ep + (wm * 64 + mt * 16) * 132 + wn * 32 + nt * 16,
                                    c[mt][nt], 132, wmma::mem_row_major);
    __syncthreads();

#pragma unroll
    for (int it = 0; it < 64; it++) {
        const int idx = it * 256 + tid;
        const int oc = idx >> 7, p = idx & 127;
        const float dm = g_demod[b * COUT + oc0 + oc];
        out[(((size_t)b * COUT + oc0 + oc) * HH + h0 + (p >> 6)) * WW + (p & 63)] =
            ep[oc * 132 + p] * dm;
    }
}

// ---------------------------------------------------------------------------
extern "C" void kernel_launch(void* const* d_in, const int* in_sizes, int n_in,
                              void* d_out, int out_size)
{
    const float* input       = (const float*)d_in[0];
    const float* style       = (const float*)d_in[1];
    const float* conv_weight = (const float*)d_in[2];
    const float* mod_weight  = (const float*)d_in[3];
    const float* mod_bias    = (const float*)d_in[4];
    float* out = (float*)d_out;

    mod_kernel<<<CIN, 256>>>(style, mod_weight, mod_bias);
    demod_kernel<<<COUT, 256>>>(conv_weight);
    wsplit_kernel<<<9 * COUT * CIN / 256, 256>>>(conv_weight);
    border_kernel<<<B * 260, 128>>>();
    xtrans_kernel<<<dim3(8, 64, 16), 256>>>(input);

    cudaFuncSetAttribute(conv_wmma_kernel,
                         cudaFuncAttributeMaxDynamicSharedMemorySize, SMEM_DYN);
    conv_wmma_kernel<<<dim3(512, 4), 256, SMEM_DYN>>>(out);
}

// round 4
// speedup vs baseline: 5.1010x; 1.4402x over previous
#include <cuda_runtime.h>
#include <cuda_fp16.h>
#include <mma.h>
#include <math.h>
#include <stddef.h>
#include <stdint.h>

using namespace nvcuda;

#define B    16
#define CIN  512
#define COUT 512
#define HH   64
#define WW   64
#define SD   512
#define EPS  1e-8f

#define MOD_SCALE  0.04419417382415922f   // 1/sqrt(512)
#define CONV_SCALE 0.014731391274719738f  // 1/sqrt(512*9)

// padded, channel-last, scaled input: [B][66][66][512] fp16 (single precision copy)
#define XP 66
static __device__ __half g_xs[(size_t)B * XP * XP * CIN];
// weights channel-last per tap: [9][512 oc][512 ci] fp16 hi/lo
static __device__ __half g_wt_hi[9 * COUT * CIN];
static __device__ __half g_wt_lo[9 * COUT * CIN];
__device__ float g_s[B * CIN];
__device__ float g_demod[B * COUT];

__device__ __forceinline__ uint32_t smem_u32(const void* p) {
    uint32_t a;
    asm("{ .reg .u64 t; cvta.to.shared.u64 t, %1; cvt.u32.u64 %0, t; }"
        : "=r"(a) : "l"(p));
    return a;
}

// ---------------------------------------------------------------------------
// Kernel 1: s[b][i] = MOD_SCALE * (style[b,:] . mod_weight[i,:]) + mod_bias[i]
// ---------------------------------------------------------------------------
__global__ __launch_bounds__(256) void mod_kernel(
    const float* __restrict__ style, const float* __restrict__ mw,
    const float* __restrict__ mb)
{
    const int i = blockIdx.x, t = threadIdx.x;
    __shared__ float sh_style[B * SD];
    __shared__ float sh_w[SD];
    __shared__ float red[8][B];
    for (int idx = t; idx < B * SD; idx += 256) sh_style[idx] = style[idx];
    for (int d = t; d < SD; d += 256)           sh_w[d] = mw[(size_t)i * SD + d];
    __syncthreads();
    float acc[B];
#pragma unroll
    for (int b = 0; b < B; b++) acc[b] = 0.f;
    for (int d = t; d < SD; d += 256) {
        const float wv = sh_w[d];
#pragma unroll
        for (int b = 0; b < B; b++) acc[b] += wv * sh_style[b * SD + d];
    }
#pragma unroll
    for (int off = 16; off > 0; off >>= 1)
#pragma unroll
        for (int b = 0; b < B; b++)
            acc[b] += __shfl_down_sync(0xffffffffu, acc[b], off);
    const int warp = t >> 5, lane = t & 31;
    if (lane == 0)
#pragma unroll
        for (int b = 0; b < B; b++) red[warp][b] = acc[b];
    __syncthreads();
    if (t < B) {
        float v = 0.f;
#pragma unroll
        for (int w = 0; w < 8; w++) v += red[w][t];
        g_s[t * CIN + i] = v * MOD_SCALE + mb[i];
    }
}

// ---------------------------------------------------------------------------
// Kernel 2: demod[b][oc] = rsqrt(CONV_SCALE^2 * sum_i wsq[oc,i]*s[b,i]^2 + eps)
// ---------------------------------------------------------------------------
__global__ __launch_bounds__(256) void demod_kernel(const float* __restrict__ cw)
{
    const int oc = blockIdx.x, t = threadIdx.x;
    __shared__ float red[8][B];
    float acc[B];
#pragma unroll
    for (int b = 0; b < B; b++) acc[b] = 0.f;
    for (int i = t; i < CIN; i += 256) {
        const float* wp = cw + ((size_t)oc * CIN + i) * 9;
        float wsq = 0.f;
#pragma unroll
        for (int k = 0; k < 9; k++) { const float v = wp[k]; wsq += v * v; }
#pragma unroll
        for (int b = 0; b < B; b++) {
            const float s = g_s[b * CIN + i];
            acc[b] += wsq * s * s;
        }
    }
#pragma unroll
    for (int off = 16; off > 0; off >>= 1)
#pragma unroll
        for (int b = 0; b < B; b++)
            acc[b] += __shfl_down_sync(0xffffffffu, acc[b], off);
    const int warp = t >> 5, lane = t & 31;
    if (lane == 0)
#pragma unroll
        for (int b = 0; b < B; b++) red[warp][b] = acc[b];
    __syncthreads();
    if (t < B) {
        float v = 0.f;
#pragma unroll
        for (int w = 0; w < 8; w++) v += red[w][t];
        g_demod[t * COUT + oc] = rsqrtf(CONV_SCALE * CONV_SCALE * v + EPS);
    }
}

// ---------------------------------------------------------------------------
// Kernel 3: weight split:  g_wt[tap][oc][ci] = fp16split(W[oc][ci][tap])
// ---------------------------------------------------------------------------
__global__ __launch_bounds__(256) void wsplit_kernel(const float* __restrict__ cw)
{
    int idx = blockIdx.x * 256 + threadIdx.x;      // 9*512*512
    int ci  = idx & 511;
    int t1  = idx >> 9;
    int oc  = t1 & 511;
    int tap = t1 >> 9;
    float v = cw[((size_t)(oc << 9) + ci) * 9 + tap];
    __half hi = __float2half(v);
    __half lo = __float2half(v - __half2float(hi));
    size_t dst = ((size_t)tap << 18) + ((size_t)oc << 9) + ci;
    g_wt_hi[dst] = hi;
    g_wt_lo[dst] = lo;
}

// ---------------------------------------------------------------------------
// Kernel 4: zero padded borders of g_xs
// ---------------------------------------------------------------------------
__global__ void border_kernel()
{
    int i = blockIdx.x;           // 16*260
    int b = i / 260, r = i % 260;
    int h, w;
    if      (r <  66) { h = 0;           w = r;        }
    else if (r < 132) { h = 65;          w = r - 66;   }
    else if (r < 196) { h = r - 132 + 1; w = 0;        }
    else              { h = r - 196 + 1; w = 65;       }
    size_t base = (((size_t)b * XP + h) * XP + w) * CIN;
    int t = threadIdx.x;          // 128 threads x 8B = 1KB = 512 halves
    *(uint2*)((char*)g_xs + base * 2 + t * 8) = make_uint2(0, 0);
}

// ---------------------------------------------------------------------------
// Kernel 5: transpose + scale:  xs[b][h+1][w+1][ci] = fp16(CONV_SCALE*s*x)
// ---------------------------------------------------------------------------
__global__ __launch_bounds__(256) void xtrans_kernel(const float* __restrict__ x)
{
    const int cic = blockIdx.x, h = blockIdx.y, b = blockIdx.z;
    const int tid = threadIdx.x;
    const int ci0 = cic * 64;
    __shared__ float sT[64 * 65];
    __shared__ float sS[64];
    if (tid < 64) sS[tid] = CONV_SCALE * g_s[b * CIN + ci0 + tid];
#pragma unroll
    for (int it = 0; it < 16; it++) {
        int idx = it * 256 + tid;
        int cl = idx >> 6, w = idx & 63;
        sT[cl * 65 + w] = x[(((size_t)(b * CIN + ci0 + cl)) * HH + h) * WW + w];
    }
    __syncthreads();
#pragma unroll
    for (int it = 0; it < 16; it++) {
        int idx = it * 256 + tid;
        int w = idx >> 6, cl = idx & 63;
        float v = sS[cl] * sT[cl * 65 + w];
        size_t dst = (((size_t)b * XP + h + 1) * XP + (w + 1)) * CIN + ci0 + cl;
        g_xs[dst] = __float2half(v);
    }
}

// ---------------------------------------------------------------------------
// Kernel 6: main wmma (HMMA) implicit-GEMM conv.
// CTA: 128 oc x 128 px (2h x 64w), 8 warps (warp tile 64x32).
// K: 72 iters = 9 taps x 8 ci-chunks(64); 2-stage cp.async double buffer.
// 2-pass split (weights hi/lo, x single fp16), fp32 accum, demod in epilogue.
// ---------------------------------------------------------------------------
#define LDM 72                        // 64 halves data + 8 pad (144B rows; 8 LDSM rows cover all 32 banks)
#define ARR_BYTES (128 * LDM * 2)     // 18432
#define STAGE_BYTES (3 * ARR_BYTES)   // Ah, Al, Bx = 55296
#define SMEM_DYN (2 * STAGE_BYTES)    // 110592

__device__ __forceinline__ void load_stage(uint32_t st_u32, int iter,
                                           int b, int h0, int oc0, int tid)
{
    const int tap = iter >> 3;
    const int ci0 = (iter & 7) * 64;
    const int kh = tap / 3, kw = tap - 3 * kh;
#pragma unroll
    for (int it = 0; it < 12; it++) {
        const int op  = it * 256 + tid;
        const int arr = op >> 10;          // compile-time per `it`
        const int r   = (op >> 3) & 127;
        const int c   = op & 7;
        uint32_t dst = st_u32 + arr * ARR_BYTES + r * 144 + c * 16;
        const __half* src;
        if (arr == 0)
            src = g_wt_hi + ((size_t)tap << 18) + ((size_t)(oc0 + r) << 9) + ci0 + c * 8;
        else if (arr == 1)
            src = g_wt_lo + ((size_t)tap << 18) + ((size_t)(oc0 + r) << 9) + ci0 + c * 8;
        else
            src = g_xs + ((((size_t)b * XP) + h0 + (r >> 6) + kh) * XP
                          + (r & 63) + kw) * CIN + ci0 + c * 8;
        asm volatile("cp.async.ca.shared.global [%0], [%1], 16;"
                     :: "r"(dst), "l"(src));
    }
}

__global__ __launch_bounds__(256, 2) void conv_wmma_kernel(float* __restrict__ out)
{
    extern __shared__ char dynsmem[];
    const int tid = threadIdx.x;
    const int wid = tid >> 5;
    const int wm  = wid & 1;      // warp M block (64 oc)
    const int wn  = wid >> 1;     // warp N block (32 px)

    const int bx = blockIdx.x;    // 16 b x 32 h-groups(2h)
    const int b  = bx >> 5;
    const int h0 = (bx & 31) * 2;
    const int oc0 = blockIdx.y * 128;

    const uint32_t s_u32 = smem_u32(dynsmem);

    wmma::fragment<wmma::accumulator, 16, 16, 16, float> c[4][2];
#pragma unroll
    for (int mt = 0; mt < 4; mt++)
#pragma unroll
        for (int nt = 0; nt < 2; nt++) wmma::fill_fragment(c[mt][nt], 0.f);

    // prologue: stages 0,1
    load_stage(s_u32, 0, b, h0, oc0, tid);
    asm volatile("cp.async.commit_group;" ::: "memory");
    load_stage(s_u32 + STAGE_BYTES, 1, b, h0, oc0, tid);
    asm volatile("cp.async.commit_group;" ::: "memory");

    for (int iter = 0; iter < 72; iter++) {
        asm volatile("cp.async.wait_group 1;" ::: "memory");
        __syncthreads();

        const char* st = dynsmem + (iter & 1) * STAGE_BYTES;
        const __half* sAh = (const __half*)(st);
        const __half* sAl = (const __half*)(st + ARR_BYTES);
        const __half* sB  = (const __half*)(st + 2 * ARR_BYTES);

#pragma unroll
        for (int ks = 0; ks < 4; ks++) {
            wmma::fragment<wmma::matrix_b, 16, 16, 16, __half, wmma::col_major> bf[2];
#pragma unroll
            for (int nt = 0; nt < 2; nt++)
                wmma::load_matrix_sync(bf[nt], sB + (wn * 32 + nt * 16) * LDM + ks * 16, LDM);
#pragma unroll
            for (int mt = 0; mt < 4; mt++) {
                const int orow = wm * 64 + mt * 16;
                wmma::fragment<wmma::matrix_a, 16, 16, 16, __half, wmma::row_major> ah, al;
                wmma::load_matrix_sync(ah, sAh + orow * LDM + ks * 16, LDM);
                wmma::load_matrix_sync(al, sAl + orow * LDM + ks * 16, LDM);
#pragma unroll
                for (int nt = 0; nt < 2; nt++) {
                    wmma::mma_sync(c[mt][nt], ah, bf[nt], c[mt][nt]);
                    wmma::mma_sync(c[mt][nt], al, bf[nt], c[mt][nt]);
                }
            }
        }
        __syncthreads();
        if (iter + 2 < 72) {
            load_stage(s_u32 + ((iter & 1) ? STAGE_BYTES : 0), iter + 2, b, h0, oc0, tid);
            asm volatile("cp.async.commit_group;" ::: "memory");
        }
    }

    // epilogue: accum -> SMEM [128 oc][132 px] -> demod-scaled coalesced STG
    float* ep = (float*)dynsmem;
#pragma unroll
    for (int mt = 0; mt < 4; mt++)
#pragma unroll
        for (int nt = 0; nt < 2; nt++)
            wmma::store_matrix_sync(ep + (wm * 64 + mt * 16) * 132 + wn * 32 + nt * 16,
                                    c[mt][nt], 132, wmma::mem_row_major);
    __syncthreads();

#pragma unroll
    for (int it = 0; it < 64; it++) {
        const int idx = it * 256 + tid;
        const int oc = idx >> 7, p = idx & 127;
        const float dm = g_demod[b * COUT + oc0 + oc];
        out[(((size_t)b * COUT + oc0 + oc) * HH + h0 + (p >> 6)) * WW + (p & 63)] =
            ep[oc * 132 + p] * dm;
    }
}

// ---------------------------------------------------------------------------
extern "C" void kernel_launch(void* const* d_in, const int* in_sizes, int n_in,
                              void* d_out, int out_size)
{
    const float* input       = (const float*)d_in[0];
    const float* style       = (const float*)d_in[1];
    const float* conv_weight = (const float*)d_in[2];
    const float* mod_weight  = (const float*)d_in[3];
    const float* mod_bias    = (const float*)d_in[4];
    float* out = (float*)d_out;

    mod_kernel<<<CIN, 256>>>(style, mod_weight, mod_bias);
    demod_kernel<<<COUT, 256>>>(conv_weight);
    wsplit_kernel<<<9 * COUT * CIN / 256, 256>>>(conv_weight);
    border_kernel<<<B * 260, 128>>>();
    xtrans_kernel<<<dim3(8, 64, 16), 256>>>(input);

    cudaFuncSetAttribute(conv_wmma_kernel,
                         cudaFuncAttributeMaxDynamicSharedMemorySize, SMEM_DYN);
    conv_wmma_kernel<<<dim3(512, 4), 256, SMEM_DYN>>>(out);
}

// round 5
// speedup vs baseline: 8.6787x; 1.7014x over previous
#include <cuda_runtime.h>
#include <cuda_fp16.h>
#include <mma.h>
#include <math.h>
#include <stddef.h>
#include <stdint.h>

using namespace nvcuda;

#define B    16
#define CIN  512
#define COUT 512
#define HH   64
#define WW   64
#define SD   512
#define EPS  1e-8f

#define MOD_SCALE  0.04419417382415922f   // 1/sqrt(512)
#define CONV_SCALE 0.014731391274719738f  // 1/sqrt(512*9)

// padded, channel-last, scaled input: [B][66][66][512] fp16
#define XP 66
static __device__ __half g_xs[(size_t)B * XP * XP * CIN];
// weights channel-last per tap: [9][512 oc][512 ci] fp16
static __device__ __half g_wt[9 * COUT * CIN];
__device__ float g_s[B * CIN];
__device__ float g_demod[B * COUT];

__device__ __forceinline__ uint32_t smem_u32(const void* p) {
    uint32_t a;
    asm("{ .reg .u64 t; cvta.to.shared.u64 t, %1; cvt.u32.u64 %0, t; }"
        : "=r"(a) : "l"(p));
    return a;
}

// ---------------------------------------------------------------------------
// Kernel 1: s[b][i] = MOD_SCALE * (style[b,:] . mod_weight[i,:]) + mod_bias[i]
// ---------------------------------------------------------------------------
__global__ __launch_bounds__(256) void mod_kernel(
    const float* __restrict__ style, const float* __restrict__ mw,
    const float* __restrict__ mb)
{
    const int i = blockIdx.x, t = threadIdx.x;
    __shared__ float sh_style[B * SD];
    __shared__ float sh_w[SD];
    __shared__ float red[8][B];
    for (int idx = t; idx < B * SD; idx += 256) sh_style[idx] = style[idx];
    for (int d = t; d < SD; d += 256)           sh_w[d] = mw[(size_t)i * SD + d];
    __syncthreads();
    float acc[B];
#pragma unroll
    for (int b = 0; b < B; b++) acc[b] = 0.f;
    for (int d = t; d < SD; d += 256) {
        const float wv = sh_w[d];
#pragma unroll
        for (int b = 0; b < B; b++) acc[b] += wv * sh_style[b * SD + d];
    }
#pragma unroll
    for (int off = 16; off > 0; off >>= 1)
#pragma unroll
        for (int b = 0; b < B; b++)
            acc[b] += __shfl_down_sync(0xffffffffu, acc[b], off);
    const int warp = t >> 5, lane = t & 31;
    if (lane == 0)
#pragma unroll
        for (int b = 0; b < B; b++) red[warp][b] = acc[b];
    __syncthreads();
    if (t < B) {
        float v = 0.f;
#pragma unroll
        for (int w = 0; w < 8; w++) v += red[w][t];
        g_s[t * CIN + i] = v * MOD_SCALE + mb[i];
    }
}

// ---------------------------------------------------------------------------
// Kernel 2: demod[b][oc] = rsqrt(CONV_SCALE^2 * sum_i wsq[oc,i]*s[b,i]^2 + eps)
// ---------------------------------------------------------------------------
__global__ __launch_bounds__(256) void demod_kernel(const float* __restrict__ cw)
{
    const int oc = blockIdx.x, t = threadIdx.x;
    __shared__ float red[8][B];
    float acc[B];
#pragma unroll
    for (int b = 0; b < B; b++) acc[b] = 0.f;
    for (int i = t; i < CIN; i += 256) {
        const float* wp = cw + ((size_t)oc * CIN + i) * 9;
        float wsq = 0.f;
#pragma unroll
        for (int k = 0; k < 9; k++) { const float v = wp[k]; wsq += v * v; }
#pragma unroll
        for (int b = 0; b < B; b++) {
            const float s = g_s[b * CIN + i];
            acc[b] += wsq * s * s;
        }
    }
#pragma unroll
    for (int off = 16; off > 0; off >>= 1)
#pragma unroll
        for (int b = 0; b < B; b++)
            acc[b] += __shfl_down_sync(0xffffffffu, acc[b], off);
    const int warp = t >> 5, lane = t & 31;
    if (lane == 0)
#pragma unroll
        for (int b = 0; b < B; b++) red[warp][b] = acc[b];
    __syncthreads();
    if (t < B) {
        float v = 0.f;
#pragma unroll
        for (int w = 0; w < 8; w++) v += red[w][t];
        g_demod[t * COUT + oc] = rsqrtf(CONV_SCALE * CONV_SCALE * v + EPS);
    }
}

// ---------------------------------------------------------------------------
// Kernel 3: weight transpose: g_wt[tap][oc][ci] = fp16(W[oc][ci][tap])
// ---------------------------------------------------------------------------
__global__ __launch_bounds__(256) void wsplit_kernel(const float* __restrict__ cw)
{
    int idx = blockIdx.x * 256 + threadIdx.x;      // 9*512*512
    int ci  = idx & 511;
    int t1  = idx >> 9;
    int oc  = t1 & 511;
    int tap = t1 >> 9;
    float v = cw[((size_t)(oc << 9) + ci) * 9 + tap];
    g_wt[((size_t)tap << 18) + ((size_t)oc << 9) + ci] = __float2half(v);
}

// ---------------------------------------------------------------------------
// Kernel 4: zero padded borders of g_xs
// ---------------------------------------------------------------------------
__global__ void border_kernel()
{
    int i = blockIdx.x;           // 16*260
    int b = i / 260, r = i % 260;
    int h, w;
    if      (r <  66) { h = 0;           w = r;        }
    else if (r < 132) { h = 65;          w = r - 66;   }
    else if (r < 196) { h = r - 132 + 1; w = 0;        }
    else              { h = r - 196 + 1; w = 65;       }
    size_t base = (((size_t)b * XP + h) * XP + w) * CIN;
    int t = threadIdx.x;          // 128 threads x 8B = 1KB = 512 halves
    *(uint2*)((char*)g_xs + base * 2 + t * 8) = make_uint2(0, 0);
}

// ---------------------------------------------------------------------------
// Kernel 5: transpose + scale:  xs[b][h+1][w+1][ci] = fp16(CONV_SCALE*s*x)
// ---------------------------------------------------------------------------
__global__ __launch_bounds__(256) void xtrans_kernel(const float* __restrict__ x)
{
    const int cic = blockIdx.x, h = blockIdx.y, b = blockIdx.z;
    const int tid = threadIdx.x;
    const int ci0 = cic * 64;
    __shared__ float sT[64 * 65];
    __shared__ float sS[64];
    if (tid < 64) sS[tid] = CONV_SCALE * g_s[b * CIN + ci0 + tid];
#pragma unroll
    for (int it = 0; it < 16; it++) {
        int idx = it * 256 + tid;
        int cl = idx >> 6, w = idx & 63;
        sT[cl * 65 + w] = x[(((size_t)(b * CIN + ci0 + cl)) * HH + h) * WW + w];
    }
    __syncthreads();
#pragma unroll
    for (int it = 0; it < 16; it++) {
        int idx = it * 256 + tid;
        int w = idx >> 6, cl = idx & 63;
        float v = sS[cl] * sT[cl * 65 + w];
        size_t dst = (((size_t)b * XP + h + 1) * XP + (w + 1)) * CIN + ci0 + cl;
        g_xs[dst] = __float2half(v);
    }
}

// ---------------------------------------------------------------------------
// Kernel 6: main wmma (HMMA) implicit-GEMM conv, single-pass fp16.
// CTA: 128 oc x 128 px (2h x 64w), 8 warps (warp tile 64x32).
// K: 72 iters = 9 taps x 8 ci-chunks(64); 3-stage cp.async pipeline,
// ONE barrier per iter. fp32 accum, demod in epilogue.
// ---------------------------------------------------------------------------
#define LDM 72                        // 64 halves data + 8 pad (144B rows)
#define ARR_BYTES (128 * LDM * 2)     // 18432
#define STAGE_BYTES (2 * ARR_BYTES)   // A, B = 36864
#define NSTAGE 3
#define SMEM_DYN (NSTAGE * STAGE_BYTES)   // 110592

__device__ __forceinline__ void load_stage(uint32_t st_u32, int iter,
                                           int b, int h0, int oc0, int tid)
{
    const int tap = iter >> 3;
    const int ci0 = (iter & 7) * 64;
    const int kh = tap / 3, kw = tap - 3 * kh;
#pragma unroll
    for (int it = 0; it < 8; it++) {
        const int op  = it * 256 + tid;
        const int arr = op >> 10;          // compile-time per `it`
        const int r   = (op >> 3) & 127;
        const int c   = op & 7;
        uint32_t dst = st_u32 + arr * ARR_BYTES + r * 144 + c * 16;
        const __half* src;
        if (arr == 0)
            src = g_wt + ((size_t)tap << 18) + ((size_t)(oc0 + r) << 9) + ci0 + c * 8;
        else
            src = g_xs + ((((size_t)b * XP) + h0 + (r >> 6) + kh) * XP
                          + (r & 63) + kw) * CIN + ci0 + c * 8;
        asm volatile("cp.async.ca.shared.global [%0], [%1], 16;"
                     :: "r"(dst), "l"(src));
    }
}

__global__ __launch_bounds__(256, 2) void conv_wmma_kernel(float* __restrict__ out)
{
    extern __shared__ char dynsmem[];
    const int tid = threadIdx.x;
    const int wid = tid >> 5;
    const int wm  = wid & 1;      // warp M block (64 oc)
    const int wn  = wid >> 1;     // warp N block (32 px)

    const int bx = blockIdx.x;    // 16 b x 32 h-groups(2h)
    const int b  = bx >> 5;
    const int h0 = (bx & 31) * 2;
    const int oc0 = blockIdx.y * 128;

    const uint32_t s_u32 = smem_u32(dynsmem);

    wmma::fragment<wmma::accumulator, 16, 16, 16, float> c[4][2];
#pragma unroll
    for (int mt = 0; mt < 4; mt++)
#pragma unroll
        for (int nt = 0; nt < 2; nt++) wmma::fill_fragment(c[mt][nt], 0.f);

    // prologue: stages 0,1 (NSTAGE-1 groups in flight)
    load_stage(s_u32, 0, b, h0, oc0, tid);
    asm volatile("cp.async.commit_group;" ::: "memory");
    load_stage(s_u32 + STAGE_BYTES, 1, b, h0, oc0, tid);
    asm volatile("cp.async.commit_group;" ::: "memory");

    int slot = 0;
    for (int iter = 0; iter < 72; iter++) {
        asm volatile("cp.async.wait_group 1;" ::: "memory");
        __syncthreads();

        // issue load for iter+2 into slot (iter+2)%3 == (slot+2)%3
        // (safe: that slot held stage iter-1, fully consumed before this barrier)
        if (iter + 2 < 72) {
            int ns = slot + 2; if (ns >= NSTAGE) ns -= NSTAGE;
            load_stage(s_u32 + ns * STAGE_BYTES, iter + 2, b, h0, oc0, tid);
            asm volatile("cp.async.commit_group;" ::: "memory");
        } else {
            asm volatile("cp.async.commit_group;" ::: "memory");  // keep group count in step
        }

        const char* st = dynsmem + slot * STAGE_BYTES;
        const __half* sA = (const __half*)(st);
        const __half* sB = (const __half*)(st + ARR_BYTES);

#pragma unroll
        for (int ks = 0; ks < 4; ks++) {
            wmma::fragment<wmma::matrix_b, 16, 16, 16, __half, wmma::col_major> bf[2];
#pragma unroll
            for (int nt = 0; nt < 2; nt++)
                wmma::load_matrix_sync(bf[nt], sB + (wn * 32 + nt * 16) * LDM + ks * 16, LDM);
#pragma unroll
            for (int mt = 0; mt < 4; mt++) {
                wmma::fragment<wmma::matrix_a, 16, 16, 16, __half, wmma::row_major> af;
                wmma::load_matrix_sync(af, sA + (wm * 64 + mt * 16) * LDM + ks * 16, LDM);
#pragma unroll
                for (int nt = 0; nt < 2; nt++)
                    wmma::mma_sync(c[mt][nt], af, bf[nt], c[mt][nt]);
            }
        }

        slot++; if (slot >= NSTAGE) slot = 0;
    }
    __syncthreads();

    // epilogue: accum -> SMEM [128 oc][132 px] -> demod-scaled coalesced STG
    float* ep = (float*)dynsmem;
#pragma unroll
    for (int mt = 0; mt < 4; mt++)
#pragma unroll
        for (int nt = 0; nt < 2; nt++)
            wmma::store_matrix_sync(ep + (wm * 64 + mt * 16) * 132 + wn * 32 + nt * 16,
                                    c[mt][nt], 132, wmma::mem_row_major);
    __syncthreads();

#pragma unroll
    for (int it = 0; it < 64; it++) {
        const int idx = it * 256 + tid;
        const int oc = idx >> 7, p = idx & 127;
        const float dm = g_demod[b * COUT + oc0 + oc];
        out[(((size_t)b * COUT + oc0 + oc) * HH + h0 + (p >> 6)) * WW + (p & 63)] =
            ep[oc * 132 + p] * dm;
    }
}

// ---------------------------------------------------------------------------
extern "C" void kernel_launch(void* const* d_in, const int* in_sizes, int n_in,
                              void* d_out, int out_size)
{
    const float* input       = (const float*)d_in[0];
    const float* style       = (const float*)d_in[1];
    const float* conv_weight = (const float*)d_in[2];
    const float* mod_weight  = (const float*)d_in[3];
    const float* mod_bias    = (const float*)d_in[4];
    float* out = (float*)d_out;

    mod_kernel<<<CIN, 256>>>(style, mod_weight, mod_bias);
    demod_kernel<<<COUT, 256>>>(conv_weight);
    wsplit_kernel<<<9 * COUT * CIN / 256, 256>>>(conv_weight);
    border_kernel<<<B * 260, 128>>>();
    xtrans_kernel<<<dim3(8, 64, 16), 256>>>(input);

    cudaFuncSetAttribute(conv_wmma_kernel,
                         cudaFuncAttributeMaxDynamicSharedMemorySize, SMEM_DYN);
    conv_wmma_kernel<<<dim3(512, 4), 256, SMEM_DYN>>>(out);
}

// round 6
// speedup vs baseline: 8.9925x; 1.0362x over previous
#include <cuda_runtime.h>
#include <cuda_fp16.h>
#include <mma.h>
#include <math.h>
#include <stddef.h>
#include <stdint.h>

using namespace nvcuda;

#define B    16
#define CIN  512
#define COUT 512
#define HH   64
#define WW   64
#define SD   512
#define EPS  1e-8f

#define MOD_SCALE  0.04419417382415922f   // 1/sqrt(512)
#define CONV_SCALE 0.014731391274719738f  // 1/sqrt(512*9)

// padded, channel-last, scaled input: [B][66][66][512] fp16
#define XP 66
static __device__ __half g_xs[(size_t)B * XP * XP * CIN];
// weights channel-last per tap: [9][512 oc][512 ci] fp16
static __device__ __half g_wt[9 * COUT * CIN];
__device__ float g_s[B * CIN];
__device__ float g_demod[B * COUT];

__device__ __forceinline__ uint32_t smem_u32(const void* p) {
    uint32_t a;
    asm("{ .reg .u64 t; cvta.to.shared.u64 t, %1; cvt.u32.u64 %0, t; }"
        : "=r"(a) : "l"(p));
    return a;
}

// ---------------------------------------------------------------------------
// Kernel 1: s[b][i] = MOD_SCALE * (style[b,:] . mod_weight[i,:]) + mod_bias[i]
// ---------------------------------------------------------------------------
__global__ __launch_bounds__(256) void mod_kernel(
    const float* __restrict__ style, const float* __restrict__ mw,
    const float* __restrict__ mb)
{
    const int i = blockIdx.x, t = threadIdx.x;
    __shared__ float sh_style[B * SD];
    __shared__ float sh_w[SD];
    __shared__ float red[8][B];
    for (int idx = t; idx < B * SD; idx += 256) sh_style[idx] = style[idx];
    for (int d = t; d < SD; d += 256)           sh_w[d] = mw[(size_t)i * SD + d];
    __syncthreads();
    float acc[B];
#pragma unroll
    for (int b = 0; b < B; b++) acc[b] = 0.f;
    for (int d = t; d < SD; d += 256) {
        const float wv = sh_w[d];
#pragma unroll
        for (int b = 0; b < B; b++) acc[b] += wv * sh_style[b * SD + d];
    }
#pragma unroll
    for (int off = 16; off > 0; off >>= 1)
#pragma unroll
        for (int b = 0; b < B; b++)
            acc[b] += __shfl_down_sync(0xffffffffu, acc[b], off);
    const int warp = t >> 5, lane = t & 31;
    if (lane == 0)
#pragma unroll
        for (int b = 0; b < B; b++) red[warp][b] = acc[b];
    __syncthreads();
    if (t < B) {
        float v = 0.f;
#pragma unroll
        for (int w = 0; w < 8; w++) v += red[w][t];
        g_s[t * CIN + i] = v * MOD_SCALE + mb[i];
    }
}

// ---------------------------------------------------------------------------
// Kernel 2: demod[b][oc] = rsqrt(CONV_SCALE^2 * sum_i wsq[oc,i]*s[b,i]^2 + eps)
// ---------------------------------------------------------------------------
__global__ __launch_bounds__(256) void demod_kernel(const float* __restrict__ cw)
{
    const int oc = blockIdx.x, t = threadIdx.x;
    __shared__ float red[8][B];
    float acc[B];
#pragma unroll
    for (int b = 0; b < B; b++) acc[b] = 0.f;
    for (int i = t; i < CIN; i += 256) {
        const float* wp = cw + ((size_t)oc * CIN + i) * 9;
        float wsq = 0.f;
#pragma unroll
        for (int k = 0; k < 9; k++) { const float v = wp[k]; wsq += v * v; }
#pragma unroll
        for (int b = 0; b < B; b++) {
            const float s = g_s[b * CIN + i];
            acc[b] += wsq * s * s;
        }
    }
#pragma unroll
    for (int off = 16; off > 0; off >>= 1)
#pragma unroll
        for (int b = 0; b < B; b++)
            acc[b] += __shfl_down_sync(0xffffffffu, acc[b], off);
    const int warp = t >> 5, lane = t & 31;
    if (lane == 0)
#pragma unroll
        for (int b = 0; b < B; b++) red[warp][b] = acc[b];
    __syncthreads();
    if (t < B) {
        float v = 0.f;
#pragma unroll
        for (int w = 0; w < 8; w++) v += red[w][t];
        g_demod[t * COUT + oc] = rsqrtf(CONV_SCALE * CONV_SCALE * v + EPS);
    }
}

// ---------------------------------------------------------------------------
// Kernel 3: weight transpose: g_wt[tap][oc][ci] = fp16(W[oc][ci][tap])
// ---------------------------------------------------------------------------
__global__ __launch_bounds__(256) void wsplit_kernel(const float* __restrict__ cw)
{
    int idx = blockIdx.x * 256 + threadIdx.x;      // 9*512*512
    int ci  = idx & 511;
    int t1  = idx >> 9;
    int oc  = t1 & 511;
    int tap = t1 >> 9;
    float v = cw[((size_t)(oc << 9) + ci) * 9 + tap];
    g_wt[((size_t)tap << 18) + ((size_t)oc << 9) + ci] = __float2half(v);
}

// ---------------------------------------------------------------------------
// Kernel 4: zero padded borders of g_xs
// ---------------------------------------------------------------------------
__global__ void border_kernel()
{
    int i = blockIdx.x;           // 16*260
    int b = i / 260, r = i % 260;
    int h, w;
    if      (r <  66) { h = 0;           w = r;        }
    else if (r < 132) { h = 65;          w = r - 66;   }
    else if (r < 196) { h = r - 132 + 1; w = 0;        }
    else              { h = r - 196 + 1; w = 65;       }
    size_t base = (((size_t)b * XP + h) * XP + w) * CIN;
    int t = threadIdx.x;          // 128 threads x 8B = 1KB = 512 halves
    *(uint2*)((char*)g_xs + base * 2 + t * 8) = make_uint2(0, 0);
}

// ---------------------------------------------------------------------------
// Kernel 5: transpose + scale:  xs[b][h+1][w+1][ci] = fp16(CONV_SCALE*s*x)
// ---------------------------------------------------------------------------
__global__ __launch_bounds__(256) void xtrans_kernel(const float* __restrict__ x)
{
    const int cic = blockIdx.x, h = blockIdx.y, b = blockIdx.z;
    const int tid = threadIdx.x;
    const int ci0 = cic * 64;
    __shared__ float sT[64 * 65];
    __shared__ float sS[64];
    if (tid < 64) sS[tid] = CONV_SCALE * g_s[b * CIN + ci0 + tid];
#pragma unroll
    for (int it = 0; it < 16; it++) {
        int idx = it * 256 + tid;
        int cl = idx >> 6, w = idx & 63;
        sT[cl * 65 + w] = x[(((size_t)(b * CIN + ci0 + cl)) * HH + h) * WW + w];
    }
    __syncthreads();
#pragma unroll
    for (int it = 0; it < 16; it++) {
        int idx = it * 256 + tid;
        int w = idx >> 6, cl = idx & 63;
        float v = sS[cl] * sT[cl * 65 + w];
        size_t dst = (((size_t)b * XP + h + 1) * XP + (w + 1)) * CIN + ci0 + cl;
        g_xs[dst] = __float2half(v);
    }
}

// ---------------------------------------------------------------------------
// Kernel 6: main wmma (HMMA) implicit-GEMM conv, single-pass fp16.
// CTA: 128 oc x 256 px (4h x 64w), 8 warps, warp tile 64x64.
// K: 72 iters = 9 taps x 8 ci-chunks(64); 3-stage cp.async pipeline,
// ONE barrier per iter. fp32 accum, demod in epilogue.
// ---------------------------------------------------------------------------
#define LDM 72                           // 64 halves data + 8 pad (144B rows)
#define A_BYTES (128 * LDM * 2)          // 18432
#define B_BYTES (256 * LDM * 2)          // 36864
#define STAGE_BYTES (A_BYTES + B_BYTES)  // 55296
#define NSTAGE 3
#define SMEM_DYN (NSTAGE * STAGE_BYTES)  // 165888

__device__ __forceinline__ void load_stage(uint32_t st_u32, int iter,
                                           int b, int h0, int oc0, int tid)
{
    const int tap = iter >> 3;
    const int ci0 = (iter & 7) * 64;
    const int kh = tap / 3, kw = tap - 3 * kh;
#pragma unroll
    for (int it = 0; it < 12; it++) {
        const int op = it * 256 + tid;
        uint32_t dst;
        const __half* src;
        if (op < 1024) {                 // A: 128 oc rows (compile-time per it)
            const int r = op >> 3, c = op & 7;
            dst = st_u32 + r * 144 + c * 16;
            src = g_wt + ((size_t)tap << 18) + ((size_t)(oc0 + r) << 9) + ci0 + c * 8;
        } else {                         // B: 256 px rows
            const int idx = op - 1024;
            const int r = idx >> 3, c = idx & 7;
            dst = st_u32 + A_BYTES + r * 144 + c * 16;
            src = g_xs + ((((size_t)b * XP) + h0 + (r >> 6) + kh) * XP
                          + (r & 63) + kw) * CIN + ci0 + c * 8;
        }
        asm volatile("cp.async.ca.shared.global [%0], [%1], 16;"
                     :: "r"(dst), "l"(src));
    }
}

__global__ __launch_bounds__(256, 1) void conv_wmma_kernel(float* __restrict__ out)
{
    extern __shared__ char dynsmem[];
    const int tid = threadIdx.x;
    const int wid = tid >> 5;
    const int wm  = wid & 1;      // warp M block (64 oc)
    const int wn  = wid >> 1;     // warp N block (64 px)

    const int bx = blockIdx.x;    // 16 b x 16 h-groups(4h)
    const int b  = bx >> 4;
    const int h0 = (bx & 15) * 4;
    const int oc0 = blockIdx.y * 128;

    const uint32_t s_u32 = smem_u32(dynsmem);

    wmma::fragment<wmma::accumulator, 16, 16, 16, float> c[4][4];
#pragma unroll
    for (int mt = 0; mt < 4; mt++)
#pragma unroll
        for (int nt = 0; nt < 4; nt++) wmma::fill_fragment(c[mt][nt], 0.f);

    // prologue: stages 0,1 (NSTAGE-1 groups in flight)
    load_stage(s_u32, 0, b, h0, oc0, tid);
    asm volatile("cp.async.commit_group;" ::: "memory");
    load_stage(s_u32 + STAGE_BYTES, 1, b, h0, oc0, tid);
    asm volatile("cp.async.commit_group;" ::: "memory");

    int slot = 0;
    for (int iter = 0; iter < 72; iter++) {
        asm volatile("cp.async.wait_group 1;" ::: "memory");
        __syncthreads();

        // issue load for iter+2 into slot (slot+2)%3
        // (safe: that slot held stage iter-1, fully consumed before this barrier)
        if (iter + 2 < 72) {
            int ns = slot + 2; if (ns >= NSTAGE) ns -= NSTAGE;
            load_stage(s_u32 + ns * STAGE_BYTES, iter + 2, b, h0, oc0, tid);
            asm volatile("cp.async.commit_group;" ::: "memory");
        } else {
            asm volatile("cp.async.commit_group;" ::: "memory");  // keep group count in step
        }

        const char* st = dynsmem + slot * STAGE_BYTES;
        const __half* sA = (const __half*)(st);
        const __half* sB = (const __half*)(st + A_BYTES);

#pragma unroll
        for (int ks = 0; ks < 4; ks++) {
            wmma::fragment<wmma::matrix_b, 16, 16, 16, __half, wmma::col_major> bf[4];
#pragma unroll
            for (int nt = 0; nt < 4; nt++)
                wmma::load_matrix_sync(bf[nt], sB + (wn * 64 + nt * 16) * LDM + ks * 16, LDM);
#pragma unroll
            for (int mt = 0; mt < 4; mt++) {
                wmma::fragment<wmma::matrix_a, 16, 16, 16, __half, wmma::row_major> af;
                wmma::load_matrix_sync(af, sA + (wm * 64 + mt * 16) * LDM + ks * 16, LDM);
#pragma unroll
                for (int nt = 0; nt < 4; nt++)
                    wmma::mma_sync(c[mt][nt], af, bf[nt], c[mt][nt]);
            }
        }

        slot++; if (slot >= NSTAGE) slot = 0;
    }
    __syncthreads();

    // epilogue: accum -> SMEM [128 oc][260 px] -> demod-scaled coalesced STG
    float* ep = (float*)dynsmem;
#pragma unroll
    for (int mt = 0; mt < 4; mt++)
#pragma unroll
        for (int nt = 0; nt < 4; nt++)
            wmma::store_matrix_sync(ep + (wm * 64 + mt * 16) * 260 + wn * 64 + nt * 16,
                                    c[mt][nt], 260, wmma::mem_row_major);
    __syncthreads();

#pragma unroll
    for (int it = 0; it < 128; it++) {
        const int idx = it * 256 + tid;
        const int oc = idx >> 8, p = idx & 255;
        const float dm = g_demod[b * COUT + oc0 + oc];
        out[(((size_t)b * COUT + oc0 + oc) * HH + h0 + (p >> 6)) * WW + (p & 63)] =
            ep[oc * 260 + p] * dm;
    }
}

// ---------------------------------------------------------------------------
extern "C" void kernel_launch(void* const* d_in, const int* in_sizes, int n_in,
                              void* d_out, int out_size)
{
    const float* input       = (const float*)d_in[0];
    const float* style       = (const float*)d_in[1];
    const float* conv_weight = (const float*)d_in[2];
    const float* mod_weight  = (const float*)d_in[3];
    const float* mod_bias    = (const float*)d_in[4];
    float* out = (float*)d_out;

    mod_kernel<<<CIN, 256>>>(style, mod_weight, mod_bias);
    demod_kernel<<<COUT, 256>>>(conv_weight);
    wsplit_kernel<<<9 * COUT * CIN / 256, 256>>>(conv_weight);
    border_kernel<<<B * 260, 128>>>();
    xtrans_kernel<<<dim3(8, 64, 16), 256>>>(input);

    cudaFuncSetAttribute(conv_wmma_kernel,
                         cudaFuncAttributeMaxDynamicSharedMemorySize, SMEM_DYN);
    conv_wmma_kernel<<<dim3(256, 4), 256, SMEM_DYN>>>(out);
}

// round 7
// speedup vs baseline: 9.6787x; 1.0763x over previous
#include <cuda_runtime.h>
#include <cuda_fp16.h>
#include <mma.h>
#include <math.h>
#include <stddef.h>
#include <stdint.h>

using namespace nvcuda;

#define B    16
#define CIN  512
#define COUT 512
#define HH   64
#define WW   64
#define SD   512
#define EPS  1e-8f

#define MOD_SCALE  0.04419417382415922f   // 1/sqrt(512)
#define CONV_SCALE 0.014731391274719738f  // 1/sqrt(512*9)

// padded, channel-last, scaled input: [B][66][66][512] fp16
#define XP 66
static __device__ __half g_xs[(size_t)B * XP * XP * CIN];
// weights channel-last per tap: [9][512 oc][512 ci] fp16
static __device__ __half g_wt[9 * COUT * CIN];
__device__ float g_s[B * CIN];
__device__ float g_demod[B * COUT];

__device__ __forceinline__ uint32_t smem_u32(const void* p) {
    uint32_t a;
    asm("{ .reg .u64 t; cvta.to.shared.u64 t, %1; cvt.u32.u64 %0, t; }"
        : "=r"(a) : "l"(p));
    return a;
}

#define MBAR_INIT(a, c) \
    asm volatile("mbarrier.init.shared.b64 [%0], %1;" :: "r"(a), "r"((uint32_t)(c)) : "memory")
#define MBAR_ARRIVE(a) \
    asm volatile("mbarrier.arrive.shared.b64 _, [%0];" :: "r"(a) : "memory")
#define MBAR_WAIT(a, ph) do {                                                        \
    asm volatile("{\n\t.reg .pred P1;\n\t"                                           \
        "WL%=:\n\tmbarrier.try_wait.parity.acquire.cta.shared::cta.b64 P1, [%0], %1, 0x989680;\n\t" \
        "@P1 bra.uni WD%=;\n\tbra.uni WL%=;\n\tWD%=:\n\t}"                           \
        :: "r"(a), "r"((uint32_t)(ph)) : "memory"); } while (0)
#define CPASYNC_MBAR_ARRIVE_NOINC(a) \
    asm volatile("cp.async.mbarrier.arrive.noinc.shared.b64 [%0];" :: "r"(a) : "memory")

// ---------------------------------------------------------------------------
// Kernel 1: s[b][i] = MOD_SCALE * (style[b,:] . mod_weight[i,:]) + mod_bias[i]
// ---------------------------------------------------------------------------
__global__ __launch_bounds__(256) void mod_kernel(
    const float* __restrict__ style, const float* __restrict__ mw,
    const float* __restrict__ mb)
{
    const int i = blockIdx.x, t = threadIdx.x;
    __shared__ float sh_style[B * SD];
    __shared__ float sh_w[SD];
    __shared__ float red[8][B];
    for (int idx = t; idx < B * SD; idx += 256) sh_style[idx] = style[idx];
    for (int d = t; d < SD; d += 256)           sh_w[d] = mw[(size_t)i * SD + d];
    __syncthreads();
    float acc[B];
#pragma unroll
    for (int b = 0; b < B; b++) acc[b] = 0.f;
    for (int d = t; d < SD; d += 256) {
        const float wv = sh_w[d];
#pragma unroll
        for (int b = 0; b < B; b++) acc[b] += wv * sh_style[b * SD + d];
    }
#pragma unroll
    for (int off = 16; off > 0; off >>= 1)
#pragma unroll
        for (int b = 0; b < B; b++)
            acc[b] += __shfl_down_sync(0xffffffffu, acc[b], off);
    const int warp = t >> 5, lane = t & 31;
    if (lane == 0)
#pragma unroll
        for (int b = 0; b < B; b++) red[warp][b] = acc[b];
    __syncthreads();
    if (t < B) {
        float v = 0.f;
#pragma unroll
        for (int w = 0; w < 8; w++) v += red[w][t];
        g_s[t * CIN + i] = v * MOD_SCALE + mb[i];
    }
}

// ---------------------------------------------------------------------------
// Kernel 2: demod[b][oc] = rsqrt(CONV_SCALE^2 * sum_i wsq[oc,i]*s[b,i]^2 + eps)
// ---------------------------------------------------------------------------
__global__ __launch_bounds__(256) void demod_kernel(const float* __restrict__ cw)
{
    const int oc = blockIdx.x, t = threadIdx.x;
    __shared__ float red[8][B];
    float acc[B];
#pragma unroll
    for (int b = 0; b < B; b++) acc[b] = 0.f;
    for (int i = t; i < CIN; i += 256) {
        const float* wp = cw + ((size_t)oc * CIN + i) * 9;
        float wsq = 0.f;
#pragma unroll
        for (int k = 0; k < 9; k++) { const float v = wp[k]; wsq += v * v; }
#pragma unroll
        for (int b = 0; b < B; b++) {
            const float s = g_s[b * CIN + i];
            acc[b] += wsq * s * s;
        }
    }
#pragma unroll
    for (int off = 16; off > 0; off >>= 1)
#pragma unroll
        for (int b = 0; b < B; b++)
            acc[b] += __shfl_down_sync(0xffffffffu, acc[b], off);
    const int warp = t >> 5, lane = t & 31;
    if (lane == 0)
#pragma unroll
        for (int b = 0; b < B; b++) red[warp][b] = acc[b];
    __syncthreads();
    if (t < B) {
        float v = 0.f;
#pragma unroll
        for (int w = 0; w < 8; w++) v += red[w][t];
        g_demod[t * COUT + oc] = rsqrtf(CONV_SCALE * CONV_SCALE * v + EPS);
    }
}

// ---------------------------------------------------------------------------
// Kernel 3: weight transpose: g_wt[tap][oc][ci] = fp16(W[oc][ci][tap])
// ---------------------------------------------------------------------------
__global__ __launch_bounds__(256) void wsplit_kernel(const float* __restrict__ cw)
{
    int idx = blockIdx.x * 256 + threadIdx.x;      // 9*512*512
    int ci  = idx & 511;
    int t1  = idx >> 9;
    int oc  = t1 & 511;
    int tap = t1 >> 9;
    float v = cw[((size_t)(oc << 9) + ci) * 9 + tap];
    g_wt[((size_t)tap << 18) + ((size_t)oc << 9) + ci] = __float2half(v);
}

// ---------------------------------------------------------------------------
// Kernel 4: zero padded borders of g_xs
// ---------------------------------------------------------------------------
__global__ void border_kernel()
{
    int i = blockIdx.x;           // 16*260
    int b = i / 260, r = i % 260;
    int h, w;
    if      (r <  66) { h = 0;           w = r;        }
    else if (r < 132) { h = 65;          w = r - 66;   }
    else if (r < 196) { h = r - 132 + 1; w = 0;        }
    else              { h = r - 196 + 1; w = 65;       }
    size_t base = (((size_t)b * XP + h) * XP + w) * CIN;
    int t = threadIdx.x;          // 128 threads x 8B = 1KB = 512 halves
    *(uint2*)((char*)g_xs + base * 2 + t * 8) = make_uint2(0, 0);
}

// ---------------------------------------------------------------------------
// Kernel 5: transpose + scale:  xs[b][h+1][w+1][ci] = fp16(CONV_SCALE*s*x)
// ---------------------------------------------------------------------------
__global__ __launch_bounds__(256) void xtrans_kernel(const float* __restrict__ x)
{
    const int cic = blockIdx.x, h = blockIdx.y, b = blockIdx.z;
    const int tid = threadIdx.x;
    const int ci0 = cic * 64;
    __shared__ float sT[64 * 65];
    __shared__ float sS[64];
    if (tid < 64) sS[tid] = CONV_SCALE * g_s[b * CIN + ci0 + tid];
#pragma unroll
    for (int it = 0; it < 16; it++) {
        int idx = it * 256 + tid;
        int cl = idx >> 6, w = idx & 63;
        sT[cl * 65 + w] = x[(((size_t)(b * CIN + ci0 + cl)) * HH + h) * WW + w];
    }
    __syncthreads();
#pragma unroll
    for (int it = 0; it < 16; it++) {
        int idx = it * 256 + tid;
        int w = idx >> 6, cl = idx & 63;
        float v = sS[cl] * sT[cl * 65 + w];
        size_t dst = (((size_t)b * XP + h + 1) * XP + (w + 1)) * CIN + ci0 + cl;
        g_xs[dst] = __float2half(v);
    }
}

// ---------------------------------------------------------------------------
// Kernel 6: main wmma (HMMA) implicit-GEMM conv, warp-specialized pipeline.
// CTA: 128 oc x 256 px (4h x 64w). 10 warps: 0-7 compute (warp tile 64x64),
// 8-9 producers (cp.async + mbarrier ring, 3 slots). No __syncthreads in loop.
// fp32 accum, demod in epilogue.
// ---------------------------------------------------------------------------
#define LDM 72                           // 64 halves data + 8 pad (144B rows)
#define A_BYTES (128 * LDM * 2)          // 18432
#define B_BYTES (256 * LDM * 2)          // 36864
#define STAGE_BYTES (A_BYTES + B_BYTES)  // 55296
#define NSTAGE 3
#define SMEM_DYN (NSTAGE * STAGE_BYTES)  // 165888
#define NTHREADS 320

__global__ __launch_bounds__(NTHREADS, 1) void conv_wmma_kernel(float* __restrict__ out)
{
    extern __shared__ char dynsmem[];
    __shared__ __align__(8) uint64_t sh_mbar[2 * NSTAGE];  // full[3], empty[3]

    const int tid = threadIdx.x;
    const int wid = tid >> 5;
    const int lane = tid & 31;

    const int bx = blockIdx.x;    // 16 b x 16 h-groups(4h)
    const int b  = bx >> 4;
    const int h0 = (bx & 15) * 4;
    const int oc0 = blockIdx.y * 128;

    const uint32_t s_u32 = smem_u32(dynsmem);
    const uint32_t mb_u32 = smem_u32(&sh_mbar[0]);
    // full[s] at mb_u32 + s*8, empty[s] at mb_u32 + 24 + s*8

    if (tid == 0) {
#pragma unroll
        for (int s = 0; s < NSTAGE; s++) {
            MBAR_INIT(mb_u32 + s * 8, 64);       // full: 64 producer threads
            MBAR_INIT(mb_u32 + 24 + s * 8, 8);   // empty: 8 compute warps
        }
    }
    __syncthreads();

    if (wid >= 8) {
        // ---------------- producers (warps 8-9, 64 threads) ----------------
        const int ptid = tid - 256;              // 0..63
        int slot = 0, par = 1;                   // phase-flip trick: first wait passes
        for (int iter = 0; iter < 72; iter++) {
            MBAR_WAIT(mb_u32 + 24 + slot * 8, par);

            const int tap = iter >> 3;
            const int ci0 = (iter & 7) * 64;
            const int kh = tap / 3, kw = tap - 3 * kh;
            const uint32_t st = s_u32 + slot * STAGE_BYTES;
            const __half* wbase = g_wt + ((size_t)tap << 18) + ci0;
            const __half* xbase = g_xs + ((((size_t)b * XP) + h0 + kh) * XP + kw) * CIN + ci0;
#pragma unroll
            for (int j = 0; j < 48; j++) {
                const int op = j * 64 + ptid;
                uint32_t dst;
                const __half* src;
                if (j < 16) {                    // A: ops 0..1023 (compile-time split)
                    const int r = op >> 3, c = op & 7;
                    dst = st + r * 144 + c * 16;
                    src = wbase + ((size_t)(oc0 + r) << 9) + c * 8;
                } else {                         // B: ops 1024..3071
                    const int idx = op - 1024;
                    const int r = idx >> 3, c = idx & 7;
                    dst = st + A_BYTES + r * 144 + c * 16;
                    src = xbase + ((size_t)((r >> 6) * XP + (r & 63)) << 9) + c * 8;
                }
                asm volatile("cp.async.ca.shared.global [%0], [%1], 16;"
                             :: "r"(dst), "l"(src));
            }
            CPASYNC_MBAR_ARRIVE_NOINC(mb_u32 + slot * 8);

            slot++; if (slot == NSTAGE) { slot = 0; par ^= 1; }
        }
    } else {
        // ---------------- consumers (warps 0-7) ----------------
        const int wm = wid & 1;       // warp M block (64 oc)
        const int wn = wid >> 1;      // warp N block (64 px)

        wmma::fragment<wmma::accumulator, 16, 16, 16, float> c[4][4];
#pragma unroll
        for (int mt = 0; mt < 4; mt++)
#pragma unroll
            for (int nt = 0; nt < 4; nt++) wmma::fill_fragment(c[mt][nt], 0.f);

        int slot = 0, par = 0;
        for (int iter = 0; iter < 72; iter++) {
            MBAR_WAIT(mb_u32 + slot * 8, par);

            const char* st = dynsmem + slot * STAGE_BYTES;
            const __half* sA = (const __half*)(st);
            const __half* sB = (const __half*)(st + A_BYTES);

#pragma unroll
            for (int ks = 0; ks < 4; ks++) {
                wmma::fragment<wmma::matrix_b, 16, 16, 16, __half, wmma::col_major> bf[4];
#pragma unroll
                for (int nt = 0; nt < 4; nt++)
                    wmma::load_matrix_sync(bf[nt], sB + (wn * 64 + nt * 16) * LDM + ks * 16, LDM);
#pragma unroll
                for (int mt = 0; mt < 4; mt++) {
                    wmma::fragment<wmma::matrix_a, 16, 16, 16, __half, wmma::row_major> af;
                    wmma::load_matrix_sync(af, sA + (wm * 64 + mt * 16) * LDM + ks * 16, LDM);
#pragma unroll
                    for (int nt = 0; nt < 4; nt++)
                        wmma::mma_sync(c[mt][nt], af, bf[nt], c[mt][nt]);
                }
            }
            if (lane == 0) MBAR_ARRIVE(mb_u32 + 24 + slot * 8);

            slot++; if (slot == NSTAGE) { slot = 0; par ^= 1; }
        }

        __syncthreads();   // join producers before smem reuse (they finished filling)

        // epilogue part 1: accum -> SMEM [128 oc][260 px]
        float* ep = (float*)dynsmem;
#pragma unroll
        for (int mt = 0; mt < 4; mt++)
#pragma unroll
            for (int nt = 0; nt < 4; nt++)
                wmma::store_matrix_sync(ep + (wm * 64 + mt * 16) * 260 + wn * 64 + nt * 16,
                                        c[mt][nt], 260, wmma::mem_row_major);
        goto epilogue_join;
    }
    __syncthreads();       // producers join here (matches consumers' first sync)
epilogue_join:
    __syncthreads();       // everyone: ep fully written

    // epilogue part 2: demod-scaled coalesced STG, all 320 threads
    {
        const float* ep = (const float*)dynsmem;
        for (int idx = tid; idx < 128 * 256; idx += NTHREADS) {
            const int oc = idx >> 8, p = idx & 255;
            const float dm = g_demod[b * COUT + oc0 + oc];
            out[(((size_t)b * COUT + oc0 + oc) * HH + h0 + (p >> 6)) * WW + (p & 63)] =
                ep[oc * 260 + p] * dm;
        }
    }
}

// ---------------------------------------------------------------------------
extern "C" void kernel_launch(void* const* d_in, const int* in_sizes, int n_in,
                              void* d_out, int out_size)
{
    const float* input       = (const float*)d_in[0];
    const float* style       = (const float*)d_in[1];
    const float* conv_weight = (const float*)d_in[2];
    const float* mod_weight  = (const float*)d_in[3];
    const float* mod_bias    = (const float*)d_in[4];
    float* out = (float*)d_out;

    mod_kernel<<<CIN, 256>>>(style, mod_weight, mod_bias);
    demod_kernel<<<COUT, 256>>>(conv_weight);
    wsplit_kernel<<<9 * COUT * CIN / 256, 256>>>(conv_weight);
    border_kernel<<<B * 260, 128>>>();
    xtrans_kernel<<<dim3(8, 64, 16), 256>>>(input);

    cudaFuncSetAttribute(conv_wmma_kernel,
                         cudaFuncAttributeMaxDynamicSharedMemorySize, SMEM_DYN);
    conv_wmma_kernel<<<dim3(256, 4), NTHREADS, SMEM_DYN>>>(out);
}